// round 1
// baseline (speedup 1.0000x reference)
#include <cuda_runtime.h>
#include <math.h>

#define ALPHA 1000.0f
#define NB 8192
#define ND 784
#define NH 256
#define NE 32
#define NK 512

// scratch (allocation-free rule: __device__ globals)
__device__ float g_h[NB * NH];
__device__ float g_h2[NB * NH];

// ---------------------------------------------------------------------------
// Generic tiled fp32 GEMM: C[M,N] = A[M,K] @ W[K,N] + bias, optional ReLU.
// 64x64 tile, BK=16, 256 threads, 4x4 register tile per thread.
// Requirements met by all call sites: M % 64 == 0, K % 16 == 0, N % 4 == 0.
// N guard handles N=32 and N=784 (non-multiple-of-64) cases.
// ---------------------------------------------------------------------------
template <bool RELU>
__global__ __launch_bounds__(256) void gemm_kernel(
    const float* __restrict__ A, const float* __restrict__ W,
    const float* __restrict__ bias, float* __restrict__ C,
    int M, int N, int K)
{
    __shared__ float As[16][68];  // [k][m], padded to kill store conflicts
    __shared__ float Bs[16][68];  // [k][n]

    const int tid = threadIdx.x;
    const int tx  = tid & 15;       // 0..15 -> 4 output cols each
    const int ty  = tid >> 4;       // 0..15 -> 4 output rows each
    const int m0  = blockIdx.y * 64;
    const int n0  = blockIdx.x * 64;

    const int a_row = tid >> 2;        // 0..63
    const int a_col = (tid & 3) * 4;   // 0,4,8,12
    const int b_row = tid >> 4;        // 0..15
    const int b_col = (tid & 15) * 4;  // 0..60

    float acc[4][4];
#pragma unroll
    for (int i = 0; i < 4; i++)
#pragma unroll
        for (int j = 0; j < 4; j++) acc[i][j] = 0.f;

    for (int kt = 0; kt < K; kt += 16) {
        // load A tile (coalesced float4), store transposed into As[k][m]
        float4 av = *(const float4*)&A[(size_t)(m0 + a_row) * K + kt + a_col];
        As[a_col + 0][a_row] = av.x;
        As[a_col + 1][a_row] = av.y;
        As[a_col + 2][a_row] = av.z;
        As[a_col + 3][a_row] = av.w;

        // load W tile (coalesced float4) with N guard (N is a multiple of 4)
        float4 bv = make_float4(0.f, 0.f, 0.f, 0.f);
        const int n = n0 + b_col;
        if (n < N) bv = *(const float4*)&W[(size_t)(kt + b_row) * N + n];
        *(float4*)&Bs[b_row][b_col] = bv;

        __syncthreads();
#pragma unroll
        for (int k = 0; k < 16; k++) {
            float4 a = *(const float4*)&As[k][ty * 4];
            float4 b = *(const float4*)&Bs[k][tx * 4];
            acc[0][0] += a.x * b.x; acc[0][1] += a.x * b.y; acc[0][2] += a.x * b.z; acc[0][3] += a.x * b.w;
            acc[1][0] += a.y * b.x; acc[1][1] += a.y * b.y; acc[1][2] += a.y * b.z; acc[1][3] += a.y * b.w;
            acc[2][0] += a.z * b.x; acc[2][1] += a.z * b.y; acc[2][2] += a.z * b.z; acc[2][3] += a.z * b.w;
            acc[3][0] += a.w * b.x; acc[3][1] += a.w * b.y; acc[3][2] += a.w * b.z; acc[3][3] += a.w * b.w;
        }
        __syncthreads();
    }

    const int nb = n0 + tx * 4;
    if (nb < N) {
        float4 bs = *(const float4*)&bias[nb];
#pragma unroll
        for (int i = 0; i < 4; i++) {
            const int m = m0 + ty * 4 + i;
            float4 o;
            o.x = acc[i][0] + bs.x;
            o.y = acc[i][1] + bs.y;
            o.z = acc[i][2] + bs.z;
            o.w = acc[i][3] + bs.w;
            if (RELU) {
                o.x = fmaxf(o.x, 0.f); o.y = fmaxf(o.y, 0.f);
                o.z = fmaxf(o.z, 0.f); o.w = fmaxf(o.w, 0.f);
            }
            *(float4*)&C[(size_t)m * N + nb] = o;
        }
    }
}

// ---------------------------------------------------------------------------
// Fused distances + stable softmin.
// Block = 256 threads handles 16 batch rows. cluster_reps staged in smem
// (row stride padded to 36 floats: 16B-aligned float4 reads, low conflicts).
// Each thread owns (1 row, 32 clusters): distances live in registers.
// ---------------------------------------------------------------------------
#define REPS_STRIDE 36
#define DIST_SMEM_FLOATS (NK * REPS_STRIDE + 16 * NE + 256 + 32)

__global__ __launch_bounds__(256) void dist_softmin_kernel(
    const float* __restrict__ emb, const float* __restrict__ reps,
    float* __restrict__ weighted, float* __restrict__ distances)
{
    extern __shared__ float s[];
    float* reps_s = s;                         // NK * 36
    float* emb_s  = s + NK * REPS_STRIDE;      // 16 * 32
    float* red    = emb_s + 16 * NE;           // 256
    float* rmin   = red + 256;                 // 16
    float* rsum   = rmin + 16;                 // 16

    const int tid  = threadIdx.x;
    const int brow = blockIdx.x * 16;

    // stage cluster reps (512x32) with padded stride
    const float4* repsg = (const float4*)reps;
    for (int idx = tid; idx < NK * NE / 4; idx += 256) {
        const int k  = idx >> 3;
        const int e4 = idx & 7;
        ((float4*)&reps_s[k * REPS_STRIDE])[e4] = repsg[idx];
    }
    // stage 16 embedding rows
    const float4* embg = (const float4*)(emb + (size_t)brow * NE);
    for (int idx = tid; idx < 16 * NE / 4; idx += 256)
        ((float4*)emb_s)[idx] = embg[idx];
    __syncthreads();

    const int row  = tid >> 4;  // 0..15
    const int lane = tid & 15;  // 0..15 -> 32 clusters each

    float er[NE];
#pragma unroll
    for (int e = 0; e < NE; e++) er[e] = emb_s[row * NE + e];

    float pd[32];
    float pmin = 3.4e38f;
#pragma unroll
    for (int j = 0; j < 32; j++) {
        const int k = j * 16 + lane;
        const float4* rp = (const float4*)&reps_s[k * REPS_STRIDE];
        float acc = 0.f;
#pragma unroll
        for (int e4 = 0; e4 < 8; e4++) {
            float4 r4 = rp[e4];
            float d0 = er[e4 * 4 + 0] - r4.x;
            float d1 = er[e4 * 4 + 1] - r4.y;
            float d2 = er[e4 * 4 + 2] - r4.z;
            float d3 = er[e4 * 4 + 3] - r4.w;
            acc += d0 * d0;
            acc += d1 * d1;
            acc += d2 * d2;
            acc += d3 * d3;
        }
        pd[j] = acc;
        pmin = fminf(pmin, acc);
    }

    // row min
    red[tid] = pmin;
    __syncthreads();
    if (lane == 0) {
        float m = red[row * 16];
#pragma unroll
        for (int t = 1; t < 16; t++) m = fminf(m, red[row * 16 + t]);
        rmin[row] = m;
    }
    __syncthreads();
    const float mv = rmin[row];

    // row sum of exponentials
    float psum = 0.f;
#pragma unroll
    for (int j = 0; j < 32; j++) psum += expf(-ALPHA * (pd[j] - mv));
    red[tid] = psum;
    __syncthreads();
    if (lane == 0) {
        float su = 0.f;
#pragma unroll
        for (int t = 0; t < 16; t++) su += red[row * 16 + t];
        rsum[row] = su;
    }
    __syncthreads();
    const float inv = 1.0f / rsum[row];

    const size_t base = (size_t)(brow + row) * NK;
#pragma unroll
    for (int j = 0; j < 32; j++) {
        const int k = j * 16 + lane;
        const float dv = pd[j];
        distances[base + k] = dv;
        weighted[base + k]  = dv * expf(-ALPHA * (dv - mv)) * inv;
    }
}

// ---------------------------------------------------------------------------
extern "C" void kernel_launch(void* const* d_in, const int* in_sizes, int n_in,
                              void* d_out, int out_size)
{
    const float* x    = (const float*)d_in[0];
    const float* reps = (const float*)d_in[1];
    const float* W1   = (const float*)d_in[2];
    const float* b1   = (const float*)d_in[3];
    const float* W2   = (const float*)d_in[4];
    const float* b2   = (const float*)d_in[5];
    const float* W3   = (const float*)d_in[6];
    const float* b3   = (const float*)d_in[7];
    const float* W4   = (const float*)d_in[8];
    const float* b4   = (const float*)d_in[9];

    float* out       = (float*)d_out;
    float* weighted  = out;                                           // [B,K]
    float* distances = out + (size_t)NB * NK;                         // [B,K]
    float* rec       = out + 2 * (size_t)NB * NK;                     // [B,D]
    float* emb       = out + 2 * (size_t)NB * NK + (size_t)NB * ND;   // [B,E]

    float *hbuf, *h2buf;
    cudaGetSymbolAddress((void**)&hbuf,  g_h);
    cudaGetSymbolAddress((void**)&h2buf, g_h2);

    const int smem = DIST_SMEM_FLOATS * (int)sizeof(float);
    cudaFuncSetAttribute(dist_softmin_kernel,
                         cudaFuncAttributeMaxDynamicSharedMemorySize, smem);

    // h = relu(x @ W1 + b1)
    gemm_kernel<true ><<<dim3(NH / 64, NB / 64), 256>>>(x, W1, b1, hbuf, NB, NH, ND);
    // emb = h @ W2 + b2   (written straight into the output slot)
    gemm_kernel<false><<<dim3(1, NB / 64), 256>>>(hbuf, W2, b2, emb, NB, NE, NH);
    // h2 = relu(emb @ W3 + b3)
    gemm_kernel<true ><<<dim3(NH / 64, NB / 64), 256>>>(emb, W3, b3, h2buf, NB, NH, NE);
    // reconstruction = h2 @ W4 + b4
    gemm_kernel<false><<<dim3((ND + 63) / 64, NB / 64), 256>>>(h2buf, W4, b4, rec, NB, ND, NH);
    // distances + softmin
    dist_softmin_kernel<<<NB / 16, 256, smem>>>(emb, reps, weighted, distances);
}

// round 2
// speedup vs baseline: 1.0417x; 1.0417x over previous
#include <cuda_runtime.h>
#include <math.h>

#define ALPHA 1000.0f
#define NB 8192
#define ND 784
#define NH 256
#define NE 32
#define NK 512

// scratch (allocation-free rule: __device__ globals)
__device__ float g_h[NB * NH];
__device__ float g_h2[NB * NH];

// ---------------------------------------------------------------------------
// packed f32x2 helpers (Blackwell FFMA2 path — ptxas never emits this from C++)
// ---------------------------------------------------------------------------
__device__ __forceinline__ void fma2(unsigned long long& acc,
                                     unsigned long long a, unsigned long long b) {
    asm("fma.rn.f32x2 %0, %1, %2, %0;" : "+l"(acc) : "l"(a), "l"(b));
}
__device__ __forceinline__ unsigned long long dup2(float x) {
    unsigned long long d;
    unsigned int u = __float_as_uint(x);
    asm("mov.b64 %0, {%1, %1};" : "=l"(d) : "r"(u));
    return d;
}
__device__ __forceinline__ float2 unpack2(unsigned long long v) {
    unsigned int lo, hi;
    asm("mov.b64 {%0, %1}, %2;" : "=r"(lo), "=r"(hi) : "l"(v));
    return make_float2(__uint_as_float(lo), __uint_as_float(hi));
}

// ---------------------------------------------------------------------------
// Big GEMM: C[M,N] = A[M,K] @ W[K,N] + bias (+ReLU).
// 128x128x16 tile, 256 threads, 8x8 micro-tile via fma.rn.f32x2,
// double-buffered smem. Requires M%128==0, K%16==0, N%16==0.
// ---------------------------------------------------------------------------
template <bool RELU>
__global__ __launch_bounds__(256) void gemm128(
    const float* __restrict__ A, const float* __restrict__ W,
    const float* __restrict__ bias, float* __restrict__ C,
    int M, int N, int K)
{
    __shared__ float As[2][16][132];  // [k][m], padded
    __shared__ float Bs[2][16][128];  // [k][n]

    const int tid = threadIdx.x;
    const int tx  = tid & 15;   // 8 output cols
    const int ty  = tid >> 4;   // 8 output rows
    const int m0  = blockIdx.y * 128;
    const int n0  = blockIdx.x * 128;

    const int a_row = tid >> 1;        // 0..127
    const int a_col = (tid & 1) * 8;   // 0 or 8
    const int b_row = tid >> 5;        // 0..7
    const int b_col = (tid & 31) * 4;  // 0..124

    const float* Aptr = A + (size_t)(m0 + a_row) * K + a_col;
    const int nW = n0 + b_col;
    const bool bok = (nW < N);

    unsigned long long acc[8][4];
#pragma unroll
    for (int i = 0; i < 8; i++)
#pragma unroll
        for (int j = 0; j < 4; j++) acc[i][j] = dup2(0.f);

    float4 pa0, pa1, pb0, pb1;

    // prefetch tile 0
    pa0 = *(const float4*)(Aptr + 0);
    pa1 = *(const float4*)(Aptr + 4);
    pb0 = make_float4(0.f, 0.f, 0.f, 0.f);
    pb1 = pb0;
    if (bok) {
        pb0 = *(const float4*)&W[(size_t)(b_row + 0) * N + nW];
        pb1 = *(const float4*)&W[(size_t)(b_row + 8) * N + nW];
    }
    {
        As[0][a_col + 0][a_row] = pa0.x; As[0][a_col + 1][a_row] = pa0.y;
        As[0][a_col + 2][a_row] = pa0.z; As[0][a_col + 3][a_row] = pa0.w;
        As[0][a_col + 4][a_row] = pa1.x; As[0][a_col + 5][a_row] = pa1.y;
        As[0][a_col + 6][a_row] = pa1.z; As[0][a_col + 7][a_row] = pa1.w;
        *(float4*)&Bs[0][b_row][b_col]     = pb0;
        *(float4*)&Bs[0][b_row + 8][b_col] = pb1;
    }
    __syncthreads();

    const int nt = K >> 4;
    for (int t = 0; t < nt; t++) {
        const int cur = t & 1;
        if (t + 1 < nt) {
            const int kt = (t + 1) * 16;
            pa0 = *(const float4*)(Aptr + kt);
            pa1 = *(const float4*)(Aptr + kt + 4);
            if (bok) {
                pb0 = *(const float4*)&W[(size_t)(kt + b_row) * N + nW];
                pb1 = *(const float4*)&W[(size_t)(kt + b_row + 8) * N + nW];
            }
        }
#pragma unroll
        for (int k = 0; k < 16; k++) {
            float4 av0 = *(const float4*)&As[cur][k][ty * 8];
            float4 av1 = *(const float4*)&As[cur][k][ty * 8 + 4];
            ulonglong2 bv0 = *(const ulonglong2*)&Bs[cur][k][tx * 8];
            ulonglong2 bv1 = *(const ulonglong2*)&Bs[cur][k][tx * 8 + 4];
            unsigned long long ad[8];
            ad[0] = dup2(av0.x); ad[1] = dup2(av0.y);
            ad[2] = dup2(av0.z); ad[3] = dup2(av0.w);
            ad[4] = dup2(av1.x); ad[5] = dup2(av1.y);
            ad[6] = dup2(av1.z); ad[7] = dup2(av1.w);
#pragma unroll
            for (int i = 0; i < 8; i++) {
                fma2(acc[i][0], ad[i], bv0.x);
                fma2(acc[i][1], ad[i], bv0.y);
                fma2(acc[i][2], ad[i], bv1.x);
                fma2(acc[i][3], ad[i], bv1.y);
            }
        }
        if (t + 1 < nt) {
            const int nxt = cur ^ 1;
            As[nxt][a_col + 0][a_row] = pa0.x; As[nxt][a_col + 1][a_row] = pa0.y;
            As[nxt][a_col + 2][a_row] = pa0.z; As[nxt][a_col + 3][a_row] = pa0.w;
            As[nxt][a_col + 4][a_row] = pa1.x; As[nxt][a_col + 5][a_row] = pa1.y;
            As[nxt][a_col + 6][a_row] = pa1.z; As[nxt][a_col + 7][a_row] = pa1.w;
            *(float4*)&Bs[nxt][b_row][b_col]     = pb0;
            *(float4*)&Bs[nxt][b_row + 8][b_col] = pb1;
        }
        __syncthreads();
    }

    // epilogue
    const int nb = n0 + tx * 8;
    if (nb < N) {
        float4 bias0 = *(const float4*)&bias[nb];
        float4 bias1 = *(const float4*)&bias[nb + 4];
#pragma unroll
        for (int i = 0; i < 8; i++) {
            float2 c0 = unpack2(acc[i][0]);
            float2 c1 = unpack2(acc[i][1]);
            float2 c2 = unpack2(acc[i][2]);
            float2 c3 = unpack2(acc[i][3]);
            float4 o0, o1;
            o0.x = c0.x + bias0.x; o0.y = c0.y + bias0.y;
            o0.z = c1.x + bias0.z; o0.w = c1.y + bias0.w;
            o1.x = c2.x + bias1.x; o1.y = c2.y + bias1.y;
            o1.z = c3.x + bias1.z; o1.w = c3.y + bias1.w;
            if (RELU) {
                o0.x = fmaxf(o0.x, 0.f); o0.y = fmaxf(o0.y, 0.f);
                o0.z = fmaxf(o0.z, 0.f); o0.w = fmaxf(o0.w, 0.f);
                o1.x = fmaxf(o1.x, 0.f); o1.y = fmaxf(o1.y, 0.f);
                o1.z = fmaxf(o1.z, 0.f); o1.w = fmaxf(o1.w, 0.f);
            }
            const size_t off = (size_t)(m0 + ty * 8 + i) * N + nb;
            *(float4*)&C[off]     = o0;
            *(float4*)&C[off + 4] = o1;
        }
    }
}

// ---------------------------------------------------------------------------
// Small GEMM (for N=32): 64x64 tile, 4x4 micro-tile (kept from R1).
// ---------------------------------------------------------------------------
template <bool RELU>
__global__ __launch_bounds__(256) void gemm_kernel(
    const float* __restrict__ A, const float* __restrict__ W,
    const float* __restrict__ bias, float* __restrict__ C,
    int M, int N, int K)
{
    __shared__ float As[16][68];
    __shared__ float Bs[16][68];

    const int tid = threadIdx.x;
    const int tx  = tid & 15;
    const int ty  = tid >> 4;
    const int m0  = blockIdx.y * 64;
    const int n0  = blockIdx.x * 64;

    const int a_row = tid >> 2;
    const int a_col = (tid & 3) * 4;
    const int b_row = tid >> 4;
    const int b_col = (tid & 15) * 4;

    float acc[4][4];
#pragma unroll
    for (int i = 0; i < 4; i++)
#pragma unroll
        for (int j = 0; j < 4; j++) acc[i][j] = 0.f;

    for (int kt = 0; kt < K; kt += 16) {
        float4 av = *(const float4*)&A[(size_t)(m0 + a_row) * K + kt + a_col];
        As[a_col + 0][a_row] = av.x;
        As[a_col + 1][a_row] = av.y;
        As[a_col + 2][a_row] = av.z;
        As[a_col + 3][a_row] = av.w;

        float4 bv = make_float4(0.f, 0.f, 0.f, 0.f);
        const int n = n0 + b_col;
        if (n < N) bv = *(const float4*)&W[(size_t)(kt + b_row) * N + n];
        *(float4*)&Bs[b_row][b_col] = bv;

        __syncthreads();
#pragma unroll
        for (int k = 0; k < 16; k++) {
            float4 a = *(const float4*)&As[k][ty * 4];
            float4 b = *(const float4*)&Bs[k][tx * 4];
            acc[0][0] += a.x * b.x; acc[0][1] += a.x * b.y; acc[0][2] += a.x * b.z; acc[0][3] += a.x * b.w;
            acc[1][0] += a.y * b.x; acc[1][1] += a.y * b.y; acc[1][2] += a.y * b.z; acc[1][3] += a.y * b.w;
            acc[2][0] += a.z * b.x; acc[2][1] += a.z * b.y; acc[2][2] += a.z * b.z; acc[2][3] += a.z * b.w;
            acc[3][0] += a.w * b.x; acc[3][1] += a.w * b.y; acc[3][2] += a.w * b.z; acc[3][3] += a.w * b.w;
        }
        __syncthreads();
    }

    const int nb = n0 + tx * 4;
    if (nb < N) {
        float4 bs = *(const float4*)&bias[nb];
#pragma unroll
        for (int i = 0; i < 4; i++) {
            const int m = m0 + ty * 4 + i;
            float4 o;
            o.x = acc[i][0] + bs.x;
            o.y = acc[i][1] + bs.y;
            o.z = acc[i][2] + bs.z;
            o.w = acc[i][3] + bs.w;
            if (RELU) {
                o.x = fmaxf(o.x, 0.f); o.y = fmaxf(o.y, 0.f);
                o.z = fmaxf(o.z, 0.f); o.w = fmaxf(o.w, 0.f);
            }
            *(float4*)&C[(size_t)m * N + nb] = o;
        }
    }
}

// ---------------------------------------------------------------------------
// Fused distances + stable softmin. exp cached in registers (1 MUFU per elem).
// ---------------------------------------------------------------------------
#define REPS_STRIDE 36
#define DIST_SMEM_FLOATS (NK * REPS_STRIDE + 16 * NE + 256 + 32)

__global__ __launch_bounds__(256) void dist_softmin_kernel(
    const float* __restrict__ emb, const float* __restrict__ reps,
    float* __restrict__ weighted, float* __restrict__ distances)
{
    extern __shared__ float s[];
    float* reps_s = s;                         // NK * 36
    float* emb_s  = s + NK * REPS_STRIDE;      // 16 * 32
    float* red    = emb_s + 16 * NE;           // 256
    float* rmin   = red + 256;                 // 16
    float* rsum   = rmin + 16;                 // 16

    const int tid  = threadIdx.x;
    const int brow = blockIdx.x * 16;

    const float4* repsg = (const float4*)reps;
    for (int idx = tid; idx < NK * NE / 4; idx += 256) {
        const int k  = idx >> 3;
        const int e4 = idx & 7;
        ((float4*)&reps_s[k * REPS_STRIDE])[e4] = repsg[idx];
    }
    const float4* embg = (const float4*)(emb + (size_t)brow * NE);
    for (int idx = tid; idx < 16 * NE / 4; idx += 256)
        ((float4*)emb_s)[idx] = embg[idx];
    __syncthreads();

    const int row  = tid >> 4;
    const int lane = tid & 15;

    float er[NE];
#pragma unroll
    for (int e = 0; e < NE; e++) er[e] = emb_s[row * NE + e];

    float pd[32];
    float pmin = 3.4e38f;
#pragma unroll
    for (int j = 0; j < 32; j++) {
        const int k = j * 16 + lane;
        const float4* rp = (const float4*)&reps_s[k * REPS_STRIDE];
        float acc = 0.f;
#pragma unroll
        for (int e4 = 0; e4 < 8; e4++) {
            float4 r4 = rp[e4];
            float d0 = er[e4 * 4 + 0] - r4.x;
            float d1 = er[e4 * 4 + 1] - r4.y;
            float d2 = er[e4 * 4 + 2] - r4.z;
            float d3 = er[e4 * 4 + 3] - r4.w;
            acc += d0 * d0;
            acc += d1 * d1;
            acc += d2 * d2;
            acc += d3 * d3;
        }
        pd[j] = acc;
        pmin = fminf(pmin, acc);
    }

    red[tid] = pmin;
    __syncthreads();
    if (lane == 0) {
        float m = red[row * 16];
#pragma unroll
        for (int t = 1; t < 16; t++) m = fminf(m, red[row * 16 + t]);
        rmin[row] = m;
    }
    __syncthreads();
    const float mv = rmin[row];

    float pe[32];
    float psum = 0.f;
#pragma unroll
    for (int j = 0; j < 32; j++) {
        pe[j] = expf(-ALPHA * (pd[j] - mv));
        psum += pe[j];
    }
    red[tid] = psum;
    __syncthreads();
    if (lane == 0) {
        float su = 0.f;
#pragma unroll
        for (int t = 0; t < 16; t++) su += red[row * 16 + t];
        rsum[row] = su;
    }
    __syncthreads();
    const float inv = 1.0f / rsum[row];

    const size_t base = (size_t)(brow + row) * NK;
#pragma unroll
    for (int j = 0; j < 32; j++) {
        const int k = j * 16 + lane;
        const float dv = pd[j];
        distances[base + k] = dv;
        weighted[base + k]  = dv * pe[j] * inv;
    }
}

// ---------------------------------------------------------------------------
extern "C" void kernel_launch(void* const* d_in, const int* in_sizes, int n_in,
                              void* d_out, int out_size)
{
    const float* x    = (const float*)d_in[0];
    const float* reps = (const float*)d_in[1];
    const float* W1   = (const float*)d_in[2];
    const float* b1   = (const float*)d_in[3];
    const float* W2   = (const float*)d_in[4];
    const float* b2   = (const float*)d_in[5];
    const float* W3   = (const float*)d_in[6];
    const float* b3   = (const float*)d_in[7];
    const float* W4   = (const float*)d_in[8];
    const float* b4   = (const float*)d_in[9];

    float* out       = (float*)d_out;
    float* weighted  = out;                                           // [B,K]
    float* distances = out + (size_t)NB * NK;                         // [B,K]
    float* rec       = out + 2 * (size_t)NB * NK;                     // [B,D]
    float* emb       = out + 2 * (size_t)NB * NK + (size_t)NB * ND;   // [B,E]

    float *hbuf, *h2buf;
    cudaGetSymbolAddress((void**)&hbuf,  g_h);
    cudaGetSymbolAddress((void**)&h2buf, g_h2);

    const int smem = DIST_SMEM_FLOATS * (int)sizeof(float);
    cudaFuncSetAttribute(dist_softmin_kernel,
                         cudaFuncAttributeMaxDynamicSharedMemorySize, smem);

    // h = relu(x @ W1 + b1)            [8192,784]@[784,256]
    gemm128<true ><<<dim3(NH / 128, NB / 128), 256>>>(x, W1, b1, hbuf, NB, NH, ND);
    // emb = h @ W2 + b2                [8192,256]@[256,32]
    gemm_kernel<false><<<dim3(1, NB / 64), 256>>>(hbuf, W2, b2, emb, NB, NE, NH);
    // h2 = relu(emb @ W3 + b3)         [8192,32]@[32,256]
    gemm128<true ><<<dim3(NH / 128, NB / 128), 256>>>(emb, W3, b3, h2buf, NB, NH, NE);
    // reconstruction = h2 @ W4 + b4    [8192,256]@[256,784]
    gemm128<false><<<dim3((ND + 127) / 128, NB / 128), 256>>>(h2buf, W4, b4, rec, NB, ND, NH);
    // distances + softmin
    dist_softmin_kernel<<<NB / 16, 256, smem>>>(emb, reps, weighted, distances);
}